// round 1
// baseline (speedup 1.0000x reference)
#include <cuda_runtime.h>

#define D_MODEL 1024
#define N_HEADS 16
#define D_HEAD 64
#define BATCH 2
#define SEQ 2048
#define ROWS (BATCH * SEQ)   // 4096

// ---------------- scratch (allocation-free) ----------------
__device__ float g_xn[ROWS * D_MODEL];
__device__ float g_q[ROWS * D_MODEL];
__device__ float g_k[ROWS * D_MODEL];
__device__ float g_v[ROWS * D_MODEL];
__device__ float g_ctx[ROWS * D_MODEL];

// ---------------- LayerNorm ----------------
__global__ void __launch_bounds__(256) ln_kernel(
    const float* __restrict__ X, const float* __restrict__ w,
    const float* __restrict__ b, float* __restrict__ Y)
{
    int row = blockIdx.x;
    const float* x = X + (size_t)row * D_MODEL;
    float* y = Y + (size_t)row * D_MODEL;
    int t = threadIdx.x;

    float4 v = *(const float4*)(x + t * 4);
    float s  = v.x + v.y + v.z + v.w;
    float ss = v.x * v.x + v.y * v.y + v.z * v.z + v.w * v.w;

    #pragma unroll
    for (int off = 16; off; off >>= 1) {
        s  += __shfl_xor_sync(0xffffffffu, s, off);
        ss += __shfl_xor_sync(0xffffffffu, ss, off);
    }
    __shared__ float sh_s[8], sh_ss[8];
    int wid = t >> 5, lid = t & 31;
    if (lid == 0) { sh_s[wid] = s; sh_ss[wid] = ss; }
    __syncthreads();
    if (wid == 0) {
        float s2  = (lid < 8) ? sh_s[lid]  : 0.0f;
        float ss2 = (lid < 8) ? sh_ss[lid] : 0.0f;
        #pragma unroll
        for (int off = 4; off; off >>= 1) {
            s2  += __shfl_xor_sync(0xffffffffu, s2, off);
            ss2 += __shfl_xor_sync(0xffffffffu, ss2, off);
        }
        if (lid == 0) { sh_s[0] = s2; sh_ss[0] = ss2; }
    }
    __syncthreads();
    float mean = sh_s[0] * (1.0f / D_MODEL);
    float var  = sh_ss[0] * (1.0f / D_MODEL) - mean * mean;
    float rs = rsqrtf(var + 1e-4f);

    float4 wv = *(const float4*)(w + t * 4);
    float4 bv = *(const float4*)(b + t * 4);
    float4 o;
    o.x = (v.x - mean) * rs * wv.x + bv.x;
    o.y = (v.y - mean) * rs * wv.y + bv.y;
    o.z = (v.z - mean) * rs * wv.z + bv.z;
    o.w = (v.w - mean) * rs * wv.w + bv.w;
    *(float4*)(y + t * 4) = o;
}

// ---------------- SGEMM + bias:  C[M,N] = A[M,K] @ W[K,N] + bias ----------------
#define BM 128
#define BN 128
#define BK 8
__global__ void __launch_bounds__(256) sgemm_bias(
    const float* __restrict__ A, const float* __restrict__ W,
    const float* __restrict__ bias, float* __restrict__ C,
    int M, int N, int K)
{
    __shared__ float As[BK][BM];
    __shared__ float Bs[BK][BN];

    int t = threadIdx.x;
    int m0 = blockIdx.y * BM;
    int n0 = blockIdx.x * BN;
    int tr = t >> 4, tc = t & 15;

    float acc[8][8] = {};

    int arow = t >> 1;           // 0..127
    int akq  = (t & 1) * 4;      // 0 or 4
    int brow = t >> 5;           // 0..7
    int bcq  = (t & 31) * 4;     // 0..124

    for (int k0 = 0; k0 < K; k0 += BK) {
        float4 av = *(const float4*)(A + (size_t)(m0 + arow) * K + k0 + akq);
        As[akq + 0][arow] = av.x;
        As[akq + 1][arow] = av.y;
        As[akq + 2][arow] = av.z;
        As[akq + 3][arow] = av.w;
        *(float4*)(&Bs[brow][bcq]) =
            *(const float4*)(W + (size_t)(k0 + brow) * N + n0 + bcq);
        __syncthreads();

        #pragma unroll
        for (int k = 0; k < BK; k++) {
            float a[8], bb[8];
            *(float4*)(a)     = *(float4*)(&As[k][tr * 8]);
            *(float4*)(a + 4) = *(float4*)(&As[k][tr * 8 + 4]);
            *(float4*)(bb)     = *(float4*)(&Bs[k][tc * 8]);
            *(float4*)(bb + 4) = *(float4*)(&Bs[k][tc * 8 + 4]);
            #pragma unroll
            for (int i = 0; i < 8; i++)
                #pragma unroll
                for (int j = 0; j < 8; j++)
                    acc[i][j] += a[i] * bb[j];
        }
        __syncthreads();
    }

    float bias8[8];
    #pragma unroll
    for (int j = 0; j < 8; j++) bias8[j] = bias[n0 + tc * 8 + j];

    #pragma unroll
    for (int i = 0; i < 8; i++) {
        int row = m0 + tr * 8 + i;
        float4 o0, o1;
        o0.x = acc[i][0] + bias8[0];
        o0.y = acc[i][1] + bias8[1];
        o0.z = acc[i][2] + bias8[2];
        o0.w = acc[i][3] + bias8[3];
        o1.x = acc[i][4] + bias8[4];
        o1.y = acc[i][5] + bias8[5];
        o1.z = acc[i][6] + bias8[6];
        o1.w = acc[i][7] + bias8[7];
        *(float4*)(C + (size_t)row * N + n0 + tc * 8)     = o0;
        *(float4*)(C + (size_t)row * N + n0 + tc * 8 + 4) = o1;
    }
}

// ---------------- Flash attention (causal), QT=64, KT=32 ----------------
#define QT 64
#define KT 32
__global__ void __launch_bounds__(256) attn_kernel(
    const float* __restrict__ Q, const float* __restrict__ Km,
    const float* __restrict__ V, float* __restrict__ O)
{
    __shared__ float Qs[QT][65];
    __shared__ float Ks[KT][65];
    __shared__ float Vs[KT][65];
    __shared__ float Ps[QT][33];

    int t = threadIdx.x;
    int qt_idx = (gridDim.x - 1) - blockIdx.x;  // heavy tiles first
    int q0 = qt_idx * QT;
    int bh = blockIdx.y;
    int b = bh >> 4, h = bh & 15;
    size_t base = ((size_t)b * SEQ) * D_MODEL + h * D_HEAD;

    // load Q tile (pre-scaled by 1/sqrt(Dh) = 0.125)
    {
        int row = t >> 2, c0 = (t & 3) * 16;
        const float* src = Q + base + (size_t)(q0 + row) * D_MODEL + c0;
        #pragma unroll
        for (int i = 0; i < 4; i++) {
            float4 v = *(const float4*)(src + i * 4);
            Qs[row][c0 + i * 4 + 0] = v.x * 0.125f;
            Qs[row][c0 + i * 4 + 1] = v.y * 0.125f;
            Qs[row][c0 + i * 4 + 2] = v.z * 0.125f;
            Qs[row][c0 + i * 4 + 3] = v.w * 0.125f;
        }
    }

    int tr = t >> 4, tc = t & 15;   // tr: 0..15 (4 q-rows each), tc: 0..15
    float acc[4][4] = {};
    float mrow[4] = {-1e30f, -1e30f, -1e30f, -1e30f};
    float lrow[4] = {};

    int nk = 2 * qt_idx + 2;
    for (int kt = 0; kt < nk; kt++) {
        int k0 = kt * KT;
        // load K, V tiles
        {
            int row = t >> 3, c0 = (t & 7) * 8;
            const float* ksrc = Km + base + (size_t)(k0 + row) * D_MODEL + c0;
            const float* vsrc = V  + base + (size_t)(k0 + row) * D_MODEL + c0;
            #pragma unroll
            for (int i = 0; i < 2; i++) {
                float4 kv = *(const float4*)(ksrc + i * 4);
                Ks[row][c0 + i * 4 + 0] = kv.x;
                Ks[row][c0 + i * 4 + 1] = kv.y;
                Ks[row][c0 + i * 4 + 2] = kv.z;
                Ks[row][c0 + i * 4 + 3] = kv.w;
                float4 vv = *(const float4*)(vsrc + i * 4);
                Vs[row][c0 + i * 4 + 0] = vv.x;
                Vs[row][c0 + i * 4 + 1] = vv.y;
                Vs[row][c0 + i * 4 + 2] = vv.z;
                Vs[row][c0 + i * 4 + 3] = vv.w;
            }
        }
        __syncthreads();

        // scores: 4 rows x 2 cols per thread
        float s[4][2] = {};
        #pragma unroll 8
        for (int d = 0; d < 64; d++) {
            float qv0 = Qs[tr * 4 + 0][d];
            float qv1 = Qs[tr * 4 + 1][d];
            float qv2 = Qs[tr * 4 + 2][d];
            float qv3 = Qs[tr * 4 + 3][d];
            float kv0 = Ks[tc * 2 + 0][d];
            float kv1 = Ks[tc * 2 + 1][d];
            s[0][0] += qv0 * kv0;  s[0][1] += qv0 * kv1;
            s[1][0] += qv1 * kv0;  s[1][1] += qv1 * kv1;
            s[2][0] += qv2 * kv0;  s[2][1] += qv2 * kv1;
            s[3][0] += qv3 * kv0;  s[3][1] += qv3 * kv1;
        }

        // causal mask (diagonal tiles only)
        if (k0 + KT - 1 > q0) {
            #pragma unroll
            for (int i = 0; i < 4; i++)
                #pragma unroll
                for (int j = 0; j < 2; j++)
                    if (k0 + tc * 2 + j > q0 + tr * 4 + i) s[i][j] = -1e30f;
        }

        // online softmax (row groups = 16 aligned lanes -> shfl_xor reduces)
        #pragma unroll
        for (int i = 0; i < 4; i++) {
            float mx = fmaxf(s[i][0], s[i][1]);
            #pragma unroll
            for (int off = 8; off; off >>= 1)
                mx = fmaxf(mx, __shfl_xor_sync(0xffffffffu, mx, off));
            float mnew = fmaxf(mrow[i], mx);
            float alpha = __expf(mrow[i] - mnew);
            float p0 = __expf(s[i][0] - mnew);
            float p1 = __expf(s[i][1] - mnew);
            float rsum = p0 + p1;
            #pragma unroll
            for (int off = 8; off; off >>= 1)
                rsum += __shfl_xor_sync(0xffffffffu, rsum, off);
            lrow[i] = lrow[i] * alpha + rsum;
            mrow[i] = mnew;
            #pragma unroll
            for (int j = 0; j < 4; j++) acc[i][j] *= alpha;
            Ps[tr * 4 + i][tc * 2 + 0] = p0;
            Ps[tr * 4 + i][tc * 2 + 1] = p1;
        }
        __syncthreads();

        // O += P @ V : 4 rows x 4 d-cols per thread
        #pragma unroll 8
        for (int c = 0; c < KT; c++) {
            float p0 = Ps[tr * 4 + 0][c];
            float p1 = Ps[tr * 4 + 1][c];
            float p2 = Ps[tr * 4 + 2][c];
            float p3 = Ps[tr * 4 + 3][c];
            float v0 = Vs[c][tc * 4 + 0];
            float v1 = Vs[c][tc * 4 + 1];
            float v2 = Vs[c][tc * 4 + 2];
            float v3 = Vs[c][tc * 4 + 3];
            acc[0][0] += p0 * v0; acc[0][1] += p0 * v1; acc[0][2] += p0 * v2; acc[0][3] += p0 * v3;
            acc[1][0] += p1 * v0; acc[1][1] += p1 * v1; acc[1][2] += p1 * v2; acc[1][3] += p1 * v3;
            acc[2][0] += p2 * v0; acc[2][1] += p2 * v1; acc[2][2] += p2 * v2; acc[2][3] += p2 * v3;
            acc[3][0] += p3 * v0; acc[3][1] += p3 * v1; acc[3][2] += p3 * v2; acc[3][3] += p3 * v3;
        }
        __syncthreads();
    }

    // write O / l
    #pragma unroll
    for (int i = 0; i < 4; i++) {
        float inv = 1.0f / lrow[i];
        float4 o;
        o.x = acc[i][0] * inv;
        o.y = acc[i][1] * inv;
        o.z = acc[i][2] * inv;
        o.w = acc[i][3] * inv;
        *(float4*)(O + base + (size_t)(q0 + tr * 4 + i) * D_MODEL + tc * 4) = o;
    }
}

// ---------------- launch ----------------
extern "C" void kernel_launch(void* const* d_in, const int* in_sizes, int n_in,
                              void* d_out, int out_size)
{
    const float* X    = (const float*)d_in[0];
    const float* ln_w = (const float*)d_in[1];
    const float* ln_b = (const float*)d_in[2];
    const float* Wq   = (const float*)d_in[3];
    const float* bq   = (const float*)d_in[4];
    const float* Wk   = (const float*)d_in[5];
    const float* bk   = (const float*)d_in[6];
    const float* Wv   = (const float*)d_in[7];
    const float* bv   = (const float*)d_in[8];
    const float* Wo   = (const float*)d_in[9];
    const float* bo   = (const float*)d_in[10];
    float* out = (float*)d_out;

    float *xn, *q, *k, *v, *ctx;
    cudaGetSymbolAddress((void**)&xn,  g_xn);
    cudaGetSymbolAddress((void**)&q,   g_q);
    cudaGetSymbolAddress((void**)&k,   g_k);
    cudaGetSymbolAddress((void**)&v,   g_v);
    cudaGetSymbolAddress((void**)&ctx, g_ctx);

    ln_kernel<<<ROWS, 256>>>(X, ln_w, ln_b, xn);

    dim3 gg(D_MODEL / BN, ROWS / BM);   // (8, 32)
    sgemm_bias<<<gg, 256>>>(xn, Wq, bq, q, ROWS, D_MODEL, D_MODEL);
    sgemm_bias<<<gg, 256>>>(xn, Wk, bk, k, ROWS, D_MODEL, D_MODEL);
    sgemm_bias<<<gg, 256>>>(xn, Wv, bv, v, ROWS, D_MODEL, D_MODEL);

    dim3 ga(SEQ / QT, BATCH * N_HEADS); // (32, 32)
    attn_kernel<<<ga, 256>>>(q, k, v, ctx);

    sgemm_bias<<<gg, 256>>>(ctx, Wo, bo, out, ROWS, D_MODEL, D_MODEL);
}

// round 6
// speedup vs baseline: 3.1140x; 3.1140x over previous
#include <cuda_runtime.h>
#include <cstdint>

#define D_MODEL 1024
#define N_HEADS 16
#define D_HEAD 64
#define BATCH 2
#define SEQ 2048
#define ROWS (BATCH * SEQ)   // 4096

// ---------------- scratch (allocation-free) ----------------
__device__ float g_xn[ROWS * D_MODEL];
__device__ float g_q[ROWS * D_MODEL];
__device__ float g_k[ROWS * D_MODEL];
__device__ float g_v[ROWS * D_MODEL];    // holds V in transposed [bh][d][s] layout
__device__ float g_ctx[ROWS * D_MODEL];
__device__ float g_wt[D_MODEL * D_MODEL];

// ---------------- helpers ----------------
__device__ __forceinline__ uint32_t smem_u32(const void* p) {
    uint32_t a;
    asm("{ .reg .u64 t; cvta.to.shared.u64 t, %1; cvt.u32.u64 %0, t; }" : "=r"(a) : "l"(p));
    return a;
}
__device__ __forceinline__ float rtf32(float x) {
    uint32_t u;
    asm("cvt.rna.tf32.f32 %0, %1;" : "=r"(u) : "f"(x));
    return __uint_as_float(u);
}
__device__ __forceinline__ void cp16(uint32_t s, const void* g) {
    asm volatile("cp.async.cg.shared.global [%0], [%1], 16;" :: "r"(s), "l"(g));
}
#define CP_COMMIT() asm volatile("cp.async.commit_group;" ::: "memory")
#define CP_WAIT0()  asm volatile("cp.async.wait_group 0;" ::: "memory")

__device__ __forceinline__ void mma8(float* c, uint32_t a0, uint32_t a1, uint32_t a2, uint32_t a3,
                                     uint32_t b0, uint32_t b1) {
    asm volatile(
        "mma.sync.aligned.m16n8k8.row.col.f32.tf32.tf32.f32 "
        "{%0,%1,%2,%3}, {%4,%5,%6,%7}, {%8,%9}, {%0,%1,%2,%3};"
        : "+f"(c[0]), "+f"(c[1]), "+f"(c[2]), "+f"(c[3])
        : "r"(a0), "r"(a1), "r"(a2), "r"(a3), "r"(b0), "r"(b1));
}
__device__ __forceinline__ uint32_t fu(float x) { return __float_as_uint(x); }

// ---------------- LayerNorm (tf32-rounded output) ----------------
__global__ void __launch_bounds__(256) ln_kernel(
    const float* __restrict__ X, const float* __restrict__ w,
    const float* __restrict__ b, float* __restrict__ Y)
{
    int row = blockIdx.x;
    const float* x = X + (size_t)row * D_MODEL;
    float* y = Y + (size_t)row * D_MODEL;
    int t = threadIdx.x;

    float4 v = *(const float4*)(x + t * 4);
    float s  = v.x + v.y + v.z + v.w;
    float ss = v.x * v.x + v.y * v.y + v.z * v.z + v.w * v.w;

    #pragma unroll
    for (int off = 16; off; off >>= 1) {
        s  += __shfl_xor_sync(0xffffffffu, s, off);
        ss += __shfl_xor_sync(0xffffffffu, ss, off);
    }
    __shared__ float sh_s[8], sh_ss[8];
    int wid = t >> 5, lid = t & 31;
    if (lid == 0) { sh_s[wid] = s; sh_ss[wid] = ss; }
    __syncthreads();
    if (wid == 0) {
        float s2  = (lid < 8) ? sh_s[lid]  : 0.0f;
        float ss2 = (lid < 8) ? sh_ss[lid] : 0.0f;
        #pragma unroll
        for (int off = 4; off; off >>= 1) {
            s2  += __shfl_xor_sync(0xffffffffu, s2, off);
            ss2 += __shfl_xor_sync(0xffffffffu, ss2, off);
        }
        if (lid == 0) { sh_s[0] = s2; sh_ss[0] = ss2; }
    }
    __syncthreads();
    float mean = sh_s[0] * (1.0f / D_MODEL);
    float var  = sh_ss[0] * (1.0f / D_MODEL) - mean * mean;
    float rs = rsqrtf(var + 1e-4f);

    float4 wv = *(const float4*)(w + t * 4);
    float4 bv = *(const float4*)(b + t * 4);
    float4 o;
    o.x = rtf32((v.x - mean) * rs * wv.x + bv.x);
    o.y = rtf32((v.y - mean) * rs * wv.y + bv.y);
    o.z = rtf32((v.z - mean) * rs * wv.z + bv.z);
    o.w = rtf32((v.w - mean) * rs * wv.w + bv.w);
    *(float4*)(y + t * 4) = o;
}

// ---------------- Weight transpose (tf32-rounded): Wt[n][k] = W[k][n] ----------------
__global__ void __launch_bounds__(256) transpose_tf32(
    const float* __restrict__ W, float* __restrict__ Wt)
{
    __shared__ float tile[32][33];
    int tx = threadIdx.x, ty = threadIdx.y;
    int k0 = blockIdx.y * 32, n0 = blockIdx.x * 32;
    #pragma unroll
    for (int i = 0; i < 4; i++)
        tile[ty + i * 8][tx] = W[(size_t)(k0 + ty + i * 8) * D_MODEL + n0 + tx];
    __syncthreads();
    #pragma unroll
    for (int i = 0; i < 4; i++)
        Wt[(size_t)(n0 + ty + i * 8) * D_MODEL + k0 + tx] = rtf32(tile[tx][ty + i * 8]);
}

// ---------------- tf32 mma.sync GEMM: C[M,N] = A[M,K] @ Wt[N,K]^T + bias ----------------
// mode 0: C row-major [row][1024].  mode 1: V-transposed: C[((b*16+h)*64+d)][2048] = val(row=s,col=h*64+d)
#define BM 128
#define BN 128
#define BK 32
#define LDT 36                      // padded row stride (floats)
#define GTILE (BM * LDT)            // 4608 floats per tile
#define GSMEM_BYTES (4 * GTILE * 4) // 73728

__global__ void __launch_bounds__(256, 2) gemm_mma(
    const float* __restrict__ A, const float* __restrict__ Bt,
    const float* __restrict__ bias, float* __restrict__ C, int mode)
{
    extern __shared__ __align__(16) float sm[];
    uint32_t sb = smem_u32(sm);
    int t = threadIdx.x, lane = t & 31, wid = t >> 5;
    int wm = wid >> 1, wn = wid & 1;
    int m0 = blockIdx.y * BM, n0 = blockIdx.x * BN;

    float acc[2][8][4] = {};

    int lrow = t >> 3, lseg = t & 7;   // tile loader: 128 rows x 8 float4-segs (x4 passes)

    // prologue: stage 0
    {
        uint32_t as = sb + (0 * GTILE + lrow * LDT + lseg * 4) * 4;
        uint32_t bs = sb + (1 * GTILE + lrow * LDT + lseg * 4) * 4;
        #pragma unroll
        for (int p = 0; p < 4; p++) {
            cp16(as + p * 32 * LDT * 4, A  + (size_t)(m0 + lrow + p * 32) * D_MODEL + lseg * 4);
            cp16(bs + p * 32 * LDT * 4, Bt + (size_t)(n0 + lrow + p * 32) * D_MODEL + lseg * 4);
        }
        CP_COMMIT();
    }

    for (int kc = 0; kc < D_MODEL / BK; kc++) {
        CP_WAIT0();
        __syncthreads();
        if (kc + 1 < D_MODEL / BK) {
            int nb = (kc + 1) & 1;
            int k0 = (kc + 1) * BK;
            uint32_t as = sb + ((2 * nb + 0) * GTILE + lrow * LDT + lseg * 4) * 4;
            uint32_t bs = sb + ((2 * nb + 1) * GTILE + lrow * LDT + lseg * 4) * 4;
            #pragma unroll
            for (int p = 0; p < 4; p++) {
                cp16(as + p * 32 * LDT * 4, A  + (size_t)(m0 + lrow + p * 32) * D_MODEL + k0 + lseg * 4);
                cp16(bs + p * 32 * LDT * 4, Bt + (size_t)(n0 + lrow + p * 32) * D_MODEL + k0 + lseg * 4);
            }
            CP_COMMIT();
        }
        const float* As = sm + (2 * (kc & 1) + 0) * GTILE;
        const float* Bs = sm + (2 * (kc & 1) + 1) * GTILE;

        #pragma unroll
        for (int ks = 0; ks < 4; ks++) {
            int c = ks * 8 + (lane & 3);
            uint32_t af[2][4];
            #pragma unroll
            for (int mt = 0; mt < 2; mt++) {
                int r = wm * 32 + mt * 16 + (lane >> 2);
                af[mt][0] = fu(As[r * LDT + c]);
                af[mt][1] = fu(As[(r + 8) * LDT + c]);
                af[mt][2] = fu(As[r * LDT + c + 4]);
                af[mt][3] = fu(As[(r + 8) * LDT + c + 4]);
            }
            #pragma unroll
            for (int nt = 0; nt < 8; nt++) {
                int n = wn * 64 + nt * 8 + (lane >> 2);
                uint32_t b0 = fu(Bs[n * LDT + c]);
                uint32_t b1 = fu(Bs[n * LDT + c + 4]);
                mma8(acc[0][nt], af[0][0], af[0][1], af[0][2], af[0][3], b0, b1);
                mma8(acc[1][nt], af[1][0], af[1][1], af[1][2], af[1][3], b0, b1);
            }
        }
        __syncthreads();
    }

    // epilogue
    #pragma unroll
    for (int mt = 0; mt < 2; mt++) {
        int row = m0 + wm * 32 + mt * 16 + (lane >> 2);
        #pragma unroll
        for (int nt = 0; nt < 8; nt++) {
            int col = n0 + wn * 64 + nt * 8 + (lane & 3) * 2;
            float v00 = rtf32(acc[mt][nt][0] + bias[col]);
            float v01 = rtf32(acc[mt][nt][1] + bias[col + 1]);
            float v10 = rtf32(acc[mt][nt][2] + bias[col]);
            float v11 = rtf32(acc[mt][nt][3] + bias[col + 1]);
            if (mode == 0) {
                *(float2*)(C + (size_t)row * D_MODEL + col)       = make_float2(v00, v01);
                *(float2*)(C + (size_t)(row + 8) * D_MODEL + col) = make_float2(v10, v11);
            } else {
                int b = row >> 11, s = row & 2047;
                int h = col >> 6,  d = col & 63;
                size_t base = ((size_t)((b * 16 + h) * 64 + d)) * SEQ;
                C[base + s]              = v00;
                C[base + SEQ + s]        = v01;       // d+1 (same head: d is even, <= 62)
                C[base + s + 8]          = v10;
                C[base + SEQ + s + 8]    = v11;
            }
        }
    }
}

// ---------------- Flash attention with tf32 mma.sync ----------------
// Block: 128 q-rows; iterate 64-key tiles. 8 warps, each owns 16 q-rows (full width).
#define AQ 128
#define AK 64
#define LDA 68
#define OFF_QS 0
#define OFF_KS (AQ * LDA)                 // 8704
#define OFF_VS (OFF_KS + AK * LDA)        // 13056
#define OFF_PS (OFF_VS + AK * LDA)        // 17408
#define ASMEM_FLOATS (OFF_PS + AQ * LDA)  // 26112
#define ASMEM_BYTES (ASMEM_FLOATS * 4)    // 104448

__global__ void __launch_bounds__(256, 2) attn_mma(
    const float* __restrict__ Q, const float* __restrict__ K,
    const float* __restrict__ Vt, float* __restrict__ O)
{
    extern __shared__ __align__(16) float sm[];
    uint32_t sb = smem_u32(sm);
    int t = threadIdx.x, lane = t & 31, wid = t >> 5;
    int qt = (gridDim.x - 1) - blockIdx.x;   // heavy tiles first
    int q0 = qt * AQ;
    int bh = blockIdx.y;
    int b = bh >> 4, h = bh & 15;
    int rowb = wid * 16;

    // load Q tile (128 rows x 64 floats): 2 threads/row, each 8 cp16 (32 floats)
    {
        int row = t >> 1, half = (t & 1) * 32;
        const float* src = Q + (size_t)(b * SEQ + q0 + row) * D_MODEL + h * 64 + half;
        uint32_t dst = sb + (row * LDA + half) * 4;
        #pragma unroll
        for (int p = 0; p < 8; p++) cp16(dst + p * 16, src + p * 4);
        CP_COMMIT();
    }

    float accO[8][4] = {};
    float mrow[2] = {-1e30f, -1e30f};
    float lrow[2] = {0.0f, 0.0f};

    int nk = 2 * qt + 2;
    for (int kt = 0; kt < nk; kt++) {
        int k0 = kt * AK;
        // load K (64x64 per head) and Vt (64 d-rows x 64 keys): 4 threads/row, each 4 cp16 (16 floats)
        {
            int row = t >> 2, qtr = (t & 3) * 16;
            const float* ksrc = K  + (size_t)(b * SEQ + k0 + row) * D_MODEL + h * 64 + qtr;
            const float* vsrc = Vt + (size_t)(bh * 64 + row) * SEQ + k0 + qtr;
            uint32_t kdst = sb + (OFF_KS + row * LDA + qtr) * 4;
            uint32_t vdst = sb + (OFF_VS + row * LDA + qtr) * 4;
            #pragma unroll
            for (int p = 0; p < 4; p++) {
                cp16(kdst + p * 16, ksrc + p * 4);
                cp16(vdst + p * 16, vsrc + p * 4);
            }
        }
        CP_COMMIT();
        CP_WAIT0();
        __syncthreads();

        const float* Qs = sm;
        const float* Ks = sm + OFF_KS;
        const float* Vs = sm + OFF_VS;
        float* Ps = sm + OFF_PS;

        // scores S = Q K^T (warp rows rowb..rowb+15, all 64 cols)
        float s[8][4] = {};
        #pragma unroll
        for (int ks = 0; ks < 8; ks++) {
            int c = ks * 8 + (lane & 3);
            int r = rowb + (lane >> 2);
            uint32_t a0 = fu(Qs[r * LDA + c]);
            uint32_t a1 = fu(Qs[(r + 8) * LDA + c]);
            uint32_t a2 = fu(Qs[r * LDA + c + 4]);
            uint32_t a3 = fu(Qs[(r + 8) * LDA + c + 4]);
            #pragma unroll
            for (int nt = 0; nt < 8; nt++) {
                int n = nt * 8 + (lane >> 2);
                uint32_t b0 = fu(Ks[n * LDA + c]);
                uint32_t b1 = fu(Ks[n * LDA + c + 4]);
                mma8(s[nt], a0, a1, a2, a3, b0, b1);
            }
        }
        // scale + causal mask
        #pragma unroll
        for (int nt = 0; nt < 8; nt++) {
            #pragma unroll
            for (int j = 0; j < 4; j++) s[nt][j] *= 0.125f;
        }
        if (k0 + AK - 1 > q0 + rowb) {
            int qr0 = q0 + rowb + (lane >> 2);
            #pragma unroll
            for (int nt = 0; nt < 8; nt++) {
                int kc = k0 + nt * 8 + (lane & 3) * 2;
                if (kc     > qr0    ) s[nt][0] = -1e30f;
                if (kc + 1 > qr0    ) s[nt][1] = -1e30f;
                if (kc     > qr0 + 8) s[nt][2] = -1e30f;
                if (kc + 1 > qr0 + 8) s[nt][3] = -1e30f;
            }
        }
        // warp-local online softmax (regs {0,1}=row r, {2,3}=row r+8)
        #pragma unroll
        for (int r = 0; r < 2; r++) {
            float mx = -1e30f;
            #pragma unroll
            for (int nt = 0; nt < 8; nt++)
                mx = fmaxf(mx, fmaxf(s[nt][2 * r], s[nt][2 * r + 1]));
            mx = fmaxf(mx, __shfl_xor_sync(0xffffffffu, mx, 1));
            mx = fmaxf(mx, __shfl_xor_sync(0xffffffffu, mx, 2));
            float mnew = fmaxf(mrow[r], mx);
            float alpha = __expf(mrow[r] - mnew);
            float rs = 0.0f;
            #pragma unroll
            for (int nt = 0; nt < 8; nt++) {
                float p0 = rtf32(__expf(s[nt][2 * r] - mnew));
                float p1 = rtf32(__expf(s[nt][2 * r + 1] - mnew));
                s[nt][2 * r] = p0;
                s[nt][2 * r + 1] = p1;
                rs += p0 + p1;
            }
            rs += __shfl_xor_sync(0xffffffffu, rs, 1);
            rs += __shfl_xor_sync(0xffffffffu, rs, 2);
            lrow[r] = lrow[r] * alpha + rs;
            mrow[r] = mnew;
            #pragma unroll
            for (int nt = 0; nt < 8; nt++) {
                accO[nt][2 * r]     *= alpha;
                accO[nt][2 * r + 1] *= alpha;
            }
        }
        // write P (warp-private rows)
        {
            int r = rowb + (lane >> 2);
            #pragma unroll
            for (int nt = 0; nt < 8; nt++) {
                int c = nt * 8 + (lane & 3) * 2;
                *(float2*)(Ps + r * LDA + c)       = make_float2(s[nt][0], s[nt][1]);
                *(float2*)(Ps + (r + 8) * LDA + c) = make_float2(s[nt][2], s[nt][3]);
            }
        }
        __syncwarp();

        // O += P V   (B = Vs[d][key], col-major over keys)
        #pragma unroll
        for (int ks = 0; ks < 8; ks++) {
            int c = ks * 8 + (lane & 3);
            int r = rowb + (lane >> 2);
            uint32_t a0 = fu(Ps[r * LDA + c]);
            uint32_t a1 = fu(Ps[(r + 8) * LDA + c]);
            uint32_t a2 = fu(Ps[r * LDA + c + 4]);
            uint32_t a3 = fu(Ps[(r + 8) * LDA + c + 4]);
            #pragma unroll
            for (int nt = 0; nt < 8; nt++) {
                int n = nt * 8 + (lane >> 2);
                uint32_t b0 = fu(Vs[n * LDA + c]);
                uint32_t b1 = fu(Vs[n * LDA + c + 4]);
                mma8(accO[nt], a0, a1, a2, a3, b0, b1);
            }
        }
        __syncthreads();
    }

    // write output (tf32-rounded; feeds final GEMM)
    float inv0 = 1.0f / lrow[0];
    float inv1 = 1.0f / lrow[1];
    int row = b * SEQ + q0 + rowb + (lane >> 2);
    #pragma unroll
    for (int nt = 0; nt < 8; nt++) {
        int col = h * 64 + nt * 8 + (lane & 3) * 2;
        *(float2*)(O + (size_t)row * D_MODEL + col) =
            make_float2(rtf32(accO[nt][0] * inv0), rtf32(accO[nt][1] * inv0));
        *(float2*)(O + (size_t)(row + 8) * D_MODEL + col) =
            make_float2(rtf32(accO[nt][2] * inv1), rtf32(accO[nt][3] * inv1));
    }
}

// ---------------- launch ----------------
extern "C" void kernel_launch(void* const* d_in, const int* in_sizes, int n_in,
                              void* d_out, int out_size)
{
    const float* X    = (const float*)d_in[0];
    const float* ln_w = (const float*)d_in[1];
    const float* ln_b = (const float*)d_in[2];
    const float* Wq   = (const float*)d_in[3];
    const float* bq   = (const float*)d_in[4];
    const float* Wk   = (const float*)d_in[5];
    const float* bk   = (const float*)d_in[6];
    const float* Wv   = (const float*)d_in[7];
    const float* bv   = (const float*)d_in[8];
    const float* Wo   = (const float*)d_in[9];
    const float* bo   = (const float*)d_in[10];
    float* out = (float*)d_out;

    float *xn, *q, *k, *v, *ctx, *wt;
    cudaGetSymbolAddress((void**)&xn,  g_xn);
    cudaGetSymbolAddress((void**)&q,   g_q);
    cudaGetSymbolAddress((void**)&k,   g_k);
    cudaGetSymbolAddress((void**)&v,   g_v);
    cudaGetSymbolAddress((void**)&ctx, g_ctx);
    cudaGetSymbolAddress((void**)&wt,  g_wt);

    cudaFuncSetAttribute(gemm_mma, cudaFuncAttributeMaxDynamicSharedMemorySize, GSMEM_BYTES);
    cudaFuncSetAttribute(attn_mma, cudaFuncAttributeMaxDynamicSharedMemorySize, ASMEM_BYTES);

    ln_kernel<<<ROWS, 256>>>(X, ln_w, ln_b, xn);

    dim3 tg(D_MODEL / 32, D_MODEL / 32);
    dim3 tb(32, 8);
    dim3 gg(D_MODEL / BN, ROWS / BM);   // (8, 32)

    transpose_tf32<<<tg, tb>>>(Wq, wt);
    gemm_mma<<<gg, 256, GSMEM_BYTES>>>(xn, wt, bq, q, 0);
    transpose_tf32<<<tg, tb>>>(Wk, wt);
    gemm_mma<<<gg, 256, GSMEM_BYTES>>>(xn, wt, bk, k, 0);
    transpose_tf32<<<tg, tb>>>(Wv, wt);
    gemm_mma<<<gg, 256, GSMEM_BYTES>>>(xn, wt, bv, v, 1);   // transposed V layout

    dim3 ga(SEQ / AQ, BATCH * N_HEADS);  // (16, 32)
    attn_mma<<<ga, 256, ASMEM_BYTES>>>(q, k, v, ctx);

    transpose_tf32<<<tg, tb>>>(Wo, wt);
    gemm_mma<<<gg, 256, GSMEM_BYTES>>>(ctx, wt, bo, out, 0);
}